// round 16
// baseline (speedup 1.0000x reference)
#include <cuda_runtime.h>
#include <cstdint>

#define Bn 32
#define Ln 4096
#define Fn 128
#define NLEV 12
#define TILE_L 128
#define TILES_PER_CTA 8
#define GRIDX 4
#define TOT (Bn * Ln * Fn)

// smem floats: A0 [0,16896), A1 [16896,33792), Btab [33792,50176), red [50176,51200), tab [51200,51584)
#define FO_A1 16896
#define FO_BT 33792
#define FO_RED 50176
#define FO_TAB 51200
#define MEGA_SMEM (51584 * 4)            // 206336 bytes

// ---------------- scratch ----------------
__device__ float g_coef[2][Ln];
__device__ float g_bias[2];
__device__ float g_part[Bn][GRIDX][2][Fn];
__device__ float g_statA[Bn][GRIDX][2][Fn];
__device__ float g_statB[Bn][GRIDX][2][Fn];
__device__ float4 g_Bq1[Bn][4096];           // packed tf32 C frag pairs (GEMM1)
__device__ int g_cntQ[Bn];
__device__ int g_cnt0[Bn];
__device__ int g_cnt1[Bn];
__device__ int g_cnt2[Bn];

__device__ __forceinline__ uint32_t smem_u32(const void* p) {
    uint32_t a;
    asm("{ .reg .u64 t; cvta.to.shared.u64 t, %1; cvt.u32.u64 %0, t; }" : "=r"(a) : "l"(p));
    return a;
}
__device__ __forceinline__ uint32_t f2tf32(float x) {
    uint32_t r;
    asm("cvt.rna.tf32.f32 %0, %1;" : "=r"(r) : "f"(x));
    return r;
}
__device__ __forceinline__ float tfr(float x) {
    return __uint_as_float(f2tf32(x));
}
__device__ __forceinline__ void cp16(uint32_t dst, const void* src) {
    asm volatile("cp.async.cg.shared.global [%0], [%1], 16;" :: "r"(dst), "l"(src));
}
#define CP_COMMIT() asm volatile("cp.async.commit_group;" ::: "memory")
#define CP_WAIT1()  asm volatile("cp.async.wait_group 1;" ::: "memory")
#define CP_WAIT0()  asm volatile("cp.async.wait_group 0;" ::: "memory")

#define LDSM4(r0, r1, r2, r3, addr) \
    asm volatile("ldmatrix.sync.aligned.m8n8.x4.shared.b16 {%0,%1,%2,%3}, [%4];" \
                 : "=r"(r0), "=r"(r1), "=r"(r2), "=r"(r3) : "r"(addr))

#define MMA_TF32(C, A, b0, b1) \
    asm volatile("mma.sync.aligned.m16n8k8.row.col.f32.tf32.tf32.f32 " \
                 "{%0,%1,%2,%3}, {%4,%5,%6,%7}, {%8,%9}, {%0,%1,%2,%3};" \
                 : "+f"(C[0]), "+f"(C[1]), "+f"(C[2]), "+f"(C[3]) \
                 : "r"(A[0]), "r"(A[1]), "r"(A[2]), "r"(A[3]), "r"(b0), "r"(b1))

// float-word index of att[f][j] inside the packed Btab fragment table
__device__ __forceinline__ int att_word(int f, int j) {
    return (((j >> 5) * 1024 + ((j >> 4) & 1) * 512 + (f >> 3) * 32 + (j & 7) * 4 + (f & 3)) << 2)
           + ((j >> 3) & 1) * 2 + ((f >> 2) & 1);
}
__device__ __forceinline__ float dot4a(const float* a, float4 w, float acc) {
    acc = fmaf(a[0], w.x, acc);
    acc = fmaf(a[1], w.y, acc);
    acc = fmaf(a[2], w.z, acc);
    acc = fmaf(a[3], w.w, acc);
    return acc;
}

// ---------------- 1) coefs + biases + counter reset ----------------
__global__ void coef_kernel(const float* __restrict__ qw, const float* __restrict__ qb,
                            const float* __restrict__ kw, const float* __restrict__ kb) {
    const int tid = threadIdx.x;
    int l = blockIdx.x * blockDim.x + tid;
    if (blockIdx.x == 0 && tid < Bn) {
        g_cntQ[tid] = 0;
        g_cnt0[tid] = 0;
        g_cnt1[tid] = 0;
        g_cnt2[tid] = 0;
    }
    if (l < Ln) {
        float cq = 1.f, ck = 1.f;
        #pragma unroll
        for (int i = 0; i < NLEV; i++) {
            int bit = (l >> i) & 1;
            cq *= qw[2 * i + bit];
            ck *= kw[2 * i + bit];
        }
        g_coef[0][l] = cq;
        g_coef[1][l] = ck;
    }
    if (blockIdx.x == 0 && tid == 0) {
        float bq = qb[NLEV - 1], bk = kb[NLEV - 1], pq = 1.f, pk = 1.f;
        for (int i = NLEV - 2; i >= 0; i--) {
            pq *= (qw[2 * (i + 1)] + qw[2 * (i + 1) + 1]);
            pk *= (kw[2 * (i + 1)] + kw[2 * (i + 1) + 1]);
            bq += qb[i] * pq;
            bk += kb[i] * pk;
        }
        g_bias[0] = bq;
        g_bias[1] = bk;
    }
}

// ---------------- GEMM tile loop (MODE 0: B from smem, stats only; MODE 1: B __ldg, store) ----------------
template <int MODE>
__device__ __forceinline__ void gemm_tiles(
    const float* Xin, float* Xout,
    const float4* BqG, uint32_t bq_sm,
    const uint32_t* ab32, float* Ab0, float* Ab1, uint32_t aoff,
    const float2* rsc2, const float2* rsh2,
    float2* st_s, float2* st_q,
    int tid, int gid, int tig, int wm, int wn)
{
    for (int t = 0; t < TILES_PER_CTA; t++) {
        if (t + 1 < TILES_PER_CTA) {
            const float* src = Xin + (size_t)(t + 1) * TILE_L * Fn;
            #pragma unroll
            for (int i = tid; i < 4096; i += 512)
                cp16(ab32[(t + 1) & 1] + ((i >> 5) * 132 + (i & 31) * 4) * 4, src + (size_t)i * 4);
            CP_COMMIT();
            CP_WAIT1();
        } else {
            CP_WAIT0();
        }
        __syncthreads();

        const uint32_t abase = ab32[t & 1] + aoff;
        float* const buf = (t & 1) ? Ab1 : Ab0;

        float c[2][4][4];
        #pragma unroll
        for (int mi = 0; mi < 2; mi++)
            #pragma unroll
            for (int ni = 0; ni < 4; ni++)
                #pragma unroll
                for (int j = 0; j < 4; j++) c[mi][ni][j] = 0.f;

        #pragma unroll
        for (int ks = 0; ks < 16; ks++) {
            uint32_t a[2][4];
            LDSM4(a[0][0], a[0][1], a[0][2], a[0][3], abase + ks * 32);
            LDSM4(a[1][0], a[1][1], a[1][2], a[1][3], abase + 16 * 132 * 4 + ks * 32);
            #pragma unroll
            for (int np = 0; np < 2; np++) {
                float4 bv;
                if (MODE == 0) {
                    asm volatile("ld.shared.v4.f32 {%0,%1,%2,%3}, [%4];"
                                 : "=f"(bv.x), "=f"(bv.y), "=f"(bv.z), "=f"(bv.w)
                                 : "r"(bq_sm + (uint32_t)((np * 512 + ks * 32) << 4)));
                } else {
                    bv = __ldg(BqG + np * 512 + ks * 32);
                }
                uint32_t b0 = __float_as_uint(bv.x), b1 = __float_as_uint(bv.y);
                uint32_t b2 = __float_as_uint(bv.z), b3 = __float_as_uint(bv.w);
                MMA_TF32(c[0][2 * np],     a[0], b0, b1);
                MMA_TF32(c[0][2 * np + 1], a[0], b2, b3);
                MMA_TF32(c[1][2 * np],     a[1], b0, b1);
                MMA_TF32(c[1][2 * np + 1], a[1], b2, b3);
            }
        }

        float* Yt = Xout + (size_t)t * TILE_L * Fn;
        #pragma unroll
        for (int mi = 0; mi < 2; mi++)
            #pragma unroll
            for (int ni = 0; ni < 4; ni++) {
                const int r0 = wm * 32 + mi * 16 + gid;
                const int col = wn * 32 + ni * 8 + tig * 2;
                float2 x0 = *(float2*)&buf[r0 * 132 + col];
                float2 x1 = *(float2*)&buf[(r0 + 8) * 132 + col];
                float2 o0, o1;
                if (MODE == 1) {
                    o0.x = c[mi][ni][0] + fmaf(x0.x, rsc2[ni].x, rsh2[ni].x);
                    o0.y = c[mi][ni][1] + fmaf(x0.y, rsc2[ni].y, rsh2[ni].y);
                    o1.x = c[mi][ni][2] + fmaf(x1.x, rsc2[ni].x, rsh2[ni].x);
                    o1.y = c[mi][ni][3] + fmaf(x1.y, rsc2[ni].y, rsh2[ni].y);
                    *(float2*)&Yt[(size_t)r0 * Fn + col] = o0;
                    *(float2*)&Yt[(size_t)(r0 + 8) * Fn + col] = o1;
                } else {
                    o0.x = c[mi][ni][0] + x0.x;
                    o0.y = c[mi][ni][1] + x0.y;
                    o1.x = c[mi][ni][2] + x1.x;
                    o1.y = c[mi][ni][3] + x1.y;
                }
                st_s[ni].x += o0.x + o1.x;
                st_s[ni].y += o0.y + o1.y;
                st_q[ni].x += fmaf(o0.x, o0.x, o1.x * o1.x);
                st_q[ni].y += fmaf(o0.y, o0.y, o1.y * o1.y);
            }
        __syncthreads();
    }
}

__device__ __forceinline__ void reduce_stats(
    float2* st_s, float2* st_q, float4* red,
    int tid, int w, int gid, int tig, float* srow, float* qrow)
{
    #pragma unroll
    for (int ni = 0; ni < 4; ni++) {
        #pragma unroll
        for (int off = 4; off < 32; off <<= 1) {
            st_s[ni].x += __shfl_xor_sync(0xFFFFFFFFu, st_s[ni].x, off);
            st_s[ni].y += __shfl_xor_sync(0xFFFFFFFFu, st_s[ni].y, off);
            st_q[ni].x += __shfl_xor_sync(0xFFFFFFFFu, st_q[ni].x, off);
            st_q[ni].y += __shfl_xor_sync(0xFFFFFFFFu, st_q[ni].y, off);
        }
        if (gid == 0)
            red[w * 16 + ni * 4 + tig] = make_float4(st_s[ni].x, st_s[ni].y, st_q[ni].x, st_q[ni].y);
    }
    __syncthreads();
    if (tid < 128) {
        const int f = tid;
        const int fwn = f >> 5, fni = (f >> 3) & 3, ftg = (f >> 1) & 3, xy = f & 1;
        float s = 0.f, q = 0.f;
        #pragma unroll
        for (int m = 0; m < 4; m++) {
            float4 v = red[(m * 4 + fwn) * 16 + fni * 4 + ftg];
            s += xy ? v.y : v.x;
            q += xy ? v.w : v.z;
        }
        srow[f] = s;
        qrow[f] = q;
    }
    __syncthreads();
}

// ---------------- 2) persistent fused kernel: qk -> softmax -> GEMM0 -> C -> GEMM1 -> norm ----------------
__global__ __launch_bounds__(512, 1)
void mega(const float* __restrict__ x, const float* __restrict__ ffw,
          const float* __restrict__ ffb, const float* __restrict__ gamma,
          const float* __restrict__ beta, float* __restrict__ out)
{
    extern __shared__ float smm[];
    float* const Ab0 = smm;
    float* const Ab1 = smm + FO_A1;
    float* const Btf = smm + FO_BT;
    float4* const Bt4 = (float4*)Btf;
    float* const redf = smm + FO_RED;
    float4* const red = (float4*)redf;
    float* const tab = smm + FO_TAB;

    const int tid = threadIdx.x, lane = tid & 31, w = tid >> 5;
    const int gid = lane >> 2, tig = lane & 3;
    const int wm = w >> 2, wn = w & 3;
    const int gx = blockIdx.x, b = blockIdx.y;

    const size_t base = ((size_t)b * Ln + (size_t)gx * TILES_PER_CTA * TILE_L) * Fn;
    uint32_t ab32[2] = { smem_u32(Ab0), smem_u32(Ab1) };
    const uint32_t btab_u32 = smem_u32(Btf);
    const uint32_t lrow = lane & 15;
    const uint32_t lcol = (lane >> 4) * 4;
    const uint32_t aoff = ((wm * 32 + lrow) * 132 + lcol) * 4;
    const uint32_t bq_sm = btab_u32 + (uint32_t)((wn * 1024 + lane) << 4);

    // ===== pass A: stream x tiles, accumulate coef-weighted column sums =====
    {
        #pragma unroll
        for (int i = tid; i < 4096; i += 512)
            cp16(ab32[0] + ((i >> 5) * 132 + (i & 31) * 4) * 4, x + base + (size_t)i * 4);
        CP_COMMIT();

        float wq = 0.f, wk = 0.f;
        const int rg = tid >> 7, f = tid & 127;
        for (int t = 0; t < TILES_PER_CTA; t++) {
            if (t + 1 < TILES_PER_CTA) {
                const float* src = x + base + (size_t)(t + 1) * TILE_L * Fn;
                #pragma unroll
                for (int i = tid; i < 4096; i += 512)
                    cp16(ab32[(t + 1) & 1] + ((i >> 5) * 132 + (i & 31) * 4) * 4, src + (size_t)i * 4);
                CP_COMMIT();
                CP_WAIT1();
            } else {
                CP_WAIT0();
            }
            __syncthreads();
            const float* buf = (t & 1) ? Ab1 : Ab0;
            const int gl0 = gx * 1024 + t * 128 + rg * 32;
            #pragma unroll 8
            for (int r = 0; r < 32; r++) {
                float v = buf[(rg * 32 + r) * 132 + f];
                wq = fmaf(__ldg(&g_coef[0][gl0 + r]), v, wq);
                wk = fmaf(__ldg(&g_coef[1][gl0 + r]), v, wk);
            }
            __syncthreads();
        }
        redf[rg * 128 + f] = wq;
        redf[512 + rg * 128 + f] = wk;
        __syncthreads();
        if (tid < 128) {
            float s = 0.f, k = 0.f;
            #pragma unroll
            for (int g = 0; g < 4; g++) {
                s += redf[g * 128 + tid];
                k += redf[512 + g * 128 + tid];
            }
            g_part[b][gx][0][tid] = s;
            g_part[b][gx][1][tid] = k;
        }
        __syncthreads();
    }

    // prefetch phase-0 x tile 0 (overlaps qk sync + softmax)
    #pragma unroll
    for (int i = tid; i < 4096; i += 512)
        cp16(ab32[0] + ((i >> 5) * 132 + (i & 31) * 4) * 4, x + base + (size_t)i * 4);
    CP_COMMIT();

    // sync Q: batch qk partials complete
    if (tid == 0) {
        __threadfence();
        atomicAdd(&g_cntQ[b], 1);
        while (atomicAdd(&g_cntQ[b], 0) < GRIDX) __nanosleep(64);
    }
    __syncthreads();

    // ===== softmax + packed B0 table in smem =====
    float qs = 0.f;
    if (tid < 128) {
        float q = g_bias[0], k = g_bias[1];
        #pragma unroll
        for (int c = 0; c < GRIDX; c++) {
            q += g_part[b][c][0][tid];
            k += g_part[b][c][1][tid];
        }
        tab[tid] = k;
        qs = q * 0.08838834764831845f;
    }
    __syncthreads();
    if (tid < 128) {
        const int f = tid;
        const int fword = ((f >> 3) * 32 + (f & 3)) * 4 + ((f >> 2) & 1);
        float m = -1e30f;
        #pragma unroll 4
        for (int j = 0; j < 128; j++) m = fmaxf(m, qs * tab[j]);
        float sum = 0.f;
        #pragma unroll 4
        for (int j = 0; j < 128; j++) {
            float e = expf(qs * tab[j] - m);
            sum += e;
            int word = (((j >> 5) * 1024 + ((j >> 4) & 1) * 512 + (j & 7) * 4) << 2) + ((j >> 3) & 1) * 2 + fword;
            Btf[word] = e;
        }
        tab[128 + f] = 1.f / sum;
    }
    __syncthreads();
    // normalize + tf32-round Btab in place
    for (int i = tid; i < 4096; i += 512) {
        float4 v = Bt4[i];
        int ks = (i >> 5) & 15, tg = i & 3;
        float r0 = tab[128 + ks * 8 + tg], r1 = tab[128 + ks * 8 + tg + 4];
        v.x = tfr(v.x * r0); v.y = tfr(v.y * r1);
        v.z = tfr(v.z * r0); v.w = tfr(v.w * r1);
        Bt4[i] = v;
    }
    __syncthreads();

    float2 st_s[4], st_q[4];
    float2 unit_sc[4], zero_sh[4];
    #pragma unroll
    for (int ni = 0; ni < 4; ni++) {
        st_s[ni] = make_float2(0.f, 0.f);
        st_q[ni] = make_float2(0.f, 0.f);
        unit_sc[ni] = make_float2(1.f, 1.f);
        zero_sh[ni] = make_float2(0.f, 0.f);
    }

    // ===== phase 0: stats of x2 = x + x@att (B from smem, NO stores) =====
    gemm_tiles<0>(x + base, (float*)0, (const float4*)0, bq_sm,
                  ab32, Ab0, Ab1, aoff, unit_sc, zero_sh, st_s, st_q,
                  tid, gid, tig, wm, wn);
    reduce_stats(st_s, st_q, red, tid, w, gid, tig,
                 &g_statA[b][gx][0][0], &g_statA[b][gx][1][0]);

    // prefetch phase-1 x tile 0
    #pragma unroll
    for (int i = tid; i < 4096; i += 512)
        cp16(ab32[0] + ((i >> 5) * 132 + (i & 31) * 4) * 4, x + base + (size_t)i * 4);
    CP_COMMIT();

    // sync 0: stats complete
    if (tid == 0) {
        __threadfence();
        atomicAdd(&g_cnt0[b], 1);
        while (atomicAdd(&g_cnt0[b], 0) < GRIDX) __nanosleep(64);
    }
    __syncthreads();

    // sc / sh / rsh
    if (tid < 128) {
        float s = 0.f, q = 0.f;
        #pragma unroll
        for (int t = 0; t < GRIDX; t++) {
            s += g_statA[b][t][0][tid];
            q += g_statA[b][t][1][tid];
        }
        const float inv = 1.f / (float)Ln;
        float m = s * inv;
        float v = q * inv - m * m;
        float rs = rsqrtf(v + 1e-5f);
        float sc = rs * gamma[tid];
        tab[tid] = sc;
        tab[128 + tid] = fmaf(-m, sc, beta[tid]);
    }
    __syncthreads();
    if (tid < 128) {
        float bias2 = ffb[tid];
        const float4* wr = (const float4*)&ffw[tid * Fn];
        #pragma unroll 8
        for (int k4 = 0; k4 < 32; k4++) {
            float4 wv = __ldg(wr + k4);
            bias2 = fmaf(tab[128 + k4 * 4],     wv.x, bias2);
            bias2 = fmaf(tab[128 + k4 * 4 + 1], wv.y, bias2);
            bias2 = fmaf(tab[128 + k4 * 4 + 2], wv.z, bias2);
            bias2 = fmaf(tab[128 + k4 * 4 + 3], wv.w, bias2);
        }
        tab[256 + tid] = tab[128 + tid] + bias2;
    }
    __syncthreads();

    // ===== build this CTA's quarter of C =====
    // C[n,f] = sc[f]*W[n,f] + att[f][n]*sc[n] + sum_j att[f][j]*sc[j]*W[n,j]
    {
        const int ksb = (tid >> 5) & 15, lane5 = tid & 31;
        const int gdb = lane5 >> 2, tgb = lane5 & 3;
        const int f0 = ksb * 8 + tgb, f1 = f0 + 4;
        const int n0 = gx * 32 + gdb, n2 = n0 + 16;
        const float4* W0 = (const float4*)&ffw[(n0)      * Fn];
        const float4* W1 = (const float4*)&ffw[(n0 + 8)  * Fn];
        const float4* W2 = (const float4*)&ffw[(n2)      * Fn];
        const float4* W3 = (const float4*)&ffw[(n2 + 8)  * Fn];
        float d[4][2] = {{0.f,0.f},{0.f,0.f},{0.f,0.f},{0.f,0.f}};
        #pragma unroll 4
        for (int j4 = 0; j4 < 32; j4++) {
            float a0[4], a1[4];
            #pragma unroll
            for (int jj = 0; jj < 4; jj++) {
                int j = j4 * 4 + jj;
                float scj = tab[j];
                a0[jj] = Btf[att_word(f0, j)] * scj;
                a1[jj] = Btf[att_word(f1, j)] * scj;
            }
            float4 wv;
            wv = __ldg(W0 + j4); d[0][0] = dot4a(a0, wv, d[0][0]); d[0][1] = dot4a(a1, wv, d[0][1]);
            wv = __ldg(W1 + j4); d[1][0] = dot4a(a0, wv, d[1][0]); d[1][1] = dot4a(a1, wv, d[1][1]);
            wv = __ldg(W2 + j4); d[2][0] = dot4a(a0, wv, d[2][0]); d[2][1] = dot4a(a1, wv, d[2][1]);
            wv = __ldg(W3 + j4); d[3][0] = dot4a(a0, wv, d[3][0]); d[3][1] = dot4a(a1, wv, d[3][1]);
        }
        const float scf0 = tab[f0], scf1 = tab[f1];
        const int nn[4] = { n0, n0 + 8, n2, n2 + 8 };
        float vv[4][2];
        #pragma unroll
        for (int q = 0; q < 4; q++) {
            int n = nn[q];
            vv[q][0] = d[q][0] + scf0 * __ldg(&ffw[n * Fn + f0]) + Btf[att_word(f0, n)] * tab[n];
            vv[q][1] = d[q][1] + scf1 * __ldg(&ffw[n * Fn + f1]) + Btf[att_word(f1, n)] * tab[n];
        }
        float4 o0, o1;
        o0.x = tfr(vv[0][0]); o0.y = tfr(vv[0][1]);
        o0.z = tfr(vv[1][0]); o0.w = tfr(vv[1][1]);
        o1.x = tfr(vv[2][0]); o1.y = tfr(vv[2][1]);
        o1.z = tfr(vv[3][0]); o1.w = tfr(vv[3][1]);
        g_Bq1[b][gx * 1024 + 0   + ksb * 32 + lane5] = o0;
        g_Bq1[b][gx * 1024 + 512 + ksb * 32 + lane5] = o1;
    }

    // sync 1: C complete
    if (tid == 0) {
        __threadfence();
        atomicAdd(&g_cnt1[b], 1);
        while (atomicAdd(&g_cnt1[b], 0) < GRIDX) __nanosleep(64);
    }
    __syncthreads();

    float2 rsc2[4], rsh2[4];
    #pragma unroll
    for (int ni = 0; ni < 4; ni++) {
        int col = wn * 32 + ni * 8 + tig * 2;
        rsc2[ni] = *(const float2*)&tab[col];
        rsh2[ni] = *(const float2*)&tab[256 + col];
        st_s[ni] = make_float2(0.f, 0.f);
        st_q[ni] = make_float2(0.f, 0.f);
    }

    // ===== phase 1: out_raw = x@C^T + x*sc + rsh =====
    gemm_tiles<1>(x + base, out + base, &g_Bq1[b][0] + wn * 1024 + lane, 0,
                  ab32, Ab0, Ab1, aoff, rsc2, rsh2, st_s, st_q,
                  tid, gid, tig, wm, wn);
    reduce_stats(st_s, st_q, red, tid, w, gid, tig,
                 &g_statB[b][gx][0][0], &g_statB[b][gx][1][0]);

    // sync 2
    if (tid == 0) {
        __threadfence();
        atomicAdd(&g_cnt2[b], 1);
        while (atomicAdd(&g_cnt2[b], 0) < GRIDX) __nanosleep(64);
    }
    __syncthreads();

    if (tid < 128) {
        float s = 0.f, q = 0.f;
        #pragma unroll
        for (int t = 0; t < GRIDX; t++) {
            s += g_statB[b][t][0][tid];
            q += g_statB[b][t][1][tid];
        }
        const float inv = 1.f / (float)Ln;
        float m = s * inv;
        float v = q * inv - m * m;
        float rs = rsqrtf(v + 1e-5f);
        float sc = rs * gamma[tid];
        tab[tid] = sc;
        tab[128 + tid] = fmaf(-m, sc, beta[tid]);
    }
    __syncthreads();

    const float4* s4t = (const float4*)tab;
    const float4* h4t = (const float4*)(tab + 128);
    for (int t = 0; t < TILES_PER_CTA; t++) {
        float4* Y4 = (float4*)(out + base + (size_t)t * TILE_L * Fn);
        #pragma unroll
        for (int j = 0; j < 8; j++) {
            int i = tid + 512 * j;
            float4 v = Y4[i];
            int fq = i & 31;
            float4 s = s4t[fq], h = h4t[fq];
            v.x = fmaf(v.x, s.x, h.x); v.y = fmaf(v.y, s.y, h.y);
            v.z = fmaf(v.z, s.z, h.z); v.w = fmaf(v.w, s.w, h.w);
            Y4[i] = v;
        }
    }
}

// ---------------- launch ----------------
extern "C" void kernel_launch(void* const* d_in, const int* in_sizes, int n_in,
                              void* d_out, int out_size) {
    const float* x     = (const float*)d_in[0];
    const float* qw    = (const float*)d_in[1];
    const float* qb    = (const float*)d_in[2];
    const float* kw    = (const float*)d_in[3];
    const float* kb    = (const float*)d_in[4];
    const float* ffw   = (const float*)d_in[5];
    const float* ffb   = (const float*)d_in[6];
    const float* gamma = (const float*)d_in[7];
    const float* beta  = (const float*)d_in[8];
    float* out = (float*)d_out;

    cudaFuncSetAttribute((const void*)mega,
                         cudaFuncAttributeMaxDynamicSharedMemorySize, MEGA_SMEM);

    coef_kernel<<<(Ln + 255) / 256, 256>>>(qw, qb, kw, kb);
    mega<<<dim3(GRIDX, Bn), 512, MEGA_SMEM>>>(x, ffw, ffb, gamma, beta, out);
}

// round 17
// speedup vs baseline: 1.0487x; 1.0487x over previous
#include <cuda_runtime.h>
#include <cstdint>

#define Bn 32
#define Ln 4096
#define Fn 128
#define NLEV 12
#define NSPLIT 8
#define TILE_L 128
#define TILES_PER_CTA 8
#define GRIDX 4
#define TOT (Bn * Ln * Fn)

// smem floats: A0/A1 double buffer, red 1024, tab 384
#define FO_A1 16896
#define FO_RED 33792
#define FO_TAB 34816
#define MEGA_SMEM ((34816 + 384) * 4)    // 140800 bytes

// ---------------- scratch ----------------
__device__ float g_coef[2][Ln];
__device__ float g_bias[2];
__device__ float g_part[Bn][NSPLIT][2][Fn];
__device__ float g_att[Bn][Fn * Fn];         // fp32 softmax rows att[f][j]
__device__ float g_statA[Bn][GRIDX][2][Fn];
__device__ float g_statB[Bn][GRIDX][2][Fn];
__device__ float4 g_Bq0[Bn][4096];           // packed tf32 B frag pairs (GEMM0: att^T)
__device__ float4 g_Bq1[Bn][4096];           // packed tf32 C frag pairs (GEMM1)
__device__ int g_cnt0[Bn];
__device__ int g_cnt1[Bn];
__device__ int g_cnt2[Bn];

__device__ __forceinline__ uint32_t smem_u32(const void* p) {
    uint32_t a;
    asm("{ .reg .u64 t; cvta.to.shared.u64 t, %1; cvt.u32.u64 %0, t; }" : "=r"(a) : "l"(p));
    return a;
}
__device__ __forceinline__ uint32_t f2tf32(float x) {
    uint32_t r;
    asm("cvt.rna.tf32.f32 %0, %1;" : "=r"(r) : "f"(x));
    return r;
}
__device__ __forceinline__ float tfr(float x) {
    return __uint_as_float(f2tf32(x));
}
__device__ __forceinline__ void cp16(uint32_t dst, const void* src) {
    asm volatile("cp.async.cg.shared.global [%0], [%1], 16;" :: "r"(dst), "l"(src));
}
#define CP_COMMIT() asm volatile("cp.async.commit_group;" ::: "memory")
#define CP_WAIT0()  asm volatile("cp.async.wait_group 0;" ::: "memory")

#define LDSM4(r0, r1, r2, r3, addr) \
    asm volatile("ldmatrix.sync.aligned.m8n8.x4.shared.b16 {%0,%1,%2,%3}, [%4];" \
                 : "=r"(r0), "=r"(r1), "=r"(r2), "=r"(r3) : "r"(addr))

#define MMA_TF32(C, A, b0, b1) \
    asm volatile("mma.sync.aligned.m16n8k8.row.col.f32.tf32.tf32.f32 " \
                 "{%0,%1,%2,%3}, {%4,%5,%6,%7}, {%8,%9}, {%0,%1,%2,%3};" \
                 : "+f"(C[0]), "+f"(C[1]), "+f"(C[2]), "+f"(C[3]) \
                 : "r"(A[0]), "r"(A[1]), "r"(A[2]), "r"(A[3]), "r"(b0), "r"(b1))

__device__ __forceinline__ float dot4(float4 a, float4 w, float acc) {
    acc = fmaf(a.x, w.x, acc);
    acc = fmaf(a.y, w.y, acc);
    acc = fmaf(a.z, w.z, acc);
    acc = fmaf(a.w, w.w, acc);
    return acc;
}

// ---------------- 1) coefs + biases + counter reset ----------------
__global__ void coef_kernel(const float* __restrict__ qw, const float* __restrict__ qb,
                            const float* __restrict__ kw, const float* __restrict__ kb) {
    const int tid = threadIdx.x;
    int l = blockIdx.x * blockDim.x + tid;
    if (blockIdx.x == 0 && tid < Bn) {
        g_cnt0[tid] = 0;
        g_cnt1[tid] = 0;
        g_cnt2[tid] = 0;
    }
    if (l < Ln) {
        float cq = 1.f, ck = 1.f;
        #pragma unroll
        for (int i = 0; i < NLEV; i++) {
            int bit = (l >> i) & 1;
            cq *= qw[2 * i + bit];
            ck *= kw[2 * i + bit];
        }
        g_coef[0][l] = cq;
        g_coef[1][l] = ck;
    }
    if (blockIdx.x == 0 && tid == 0) {
        float bq = qb[NLEV - 1], bk = kb[NLEV - 1], pq = 1.f, pk = 1.f;
        for (int i = NLEV - 2; i >= 0; i--) {
            pq *= (qw[2 * (i + 1)] + qw[2 * (i + 1) + 1]);
            pk *= (kw[2 * (i + 1)] + kw[2 * (i + 1) + 1]);
            bq += qb[i] * pq;
            bk += kb[i] * pk;
        }
        g_bias[0] = bq;
        g_bias[1] = bk;
    }
}

// ---------------- 2) q/k partial reductions (float4 loads) ----------------
__global__ void qk_partial(const float* __restrict__ x) {
    const int b = blockIdx.y, ls = blockIdx.x;
    const int tid = threadIdx.x;
    const int f4 = tid & 31, sub = tid >> 5;
    const int lbase = ls * 512 + sub * 64;
    const float4* xp = (const float4*)(x + ((size_t)b * Ln + lbase) * Fn) + f4;
    float4 aq = make_float4(0.f, 0.f, 0.f, 0.f);
    float4 ak = make_float4(0.f, 0.f, 0.f, 0.f);
    #pragma unroll 8
    for (int j = 0; j < 64; j++) {
        float4 v = xp[(size_t)j * 32];
        int l = lbase + j;
        float cq = g_coef[0][l], ck = g_coef[1][l];
        aq.x = fmaf(cq, v.x, aq.x); aq.y = fmaf(cq, v.y, aq.y);
        aq.z = fmaf(cq, v.z, aq.z); aq.w = fmaf(cq, v.w, aq.w);
        ak.x = fmaf(ck, v.x, ak.x); ak.y = fmaf(ck, v.y, ak.y);
        ak.z = fmaf(ck, v.z, ak.z); ak.w = fmaf(ck, v.w, ak.w);
    }
    __shared__ float4 rq[8][32], rk[8][32];
    rq[sub][f4] = aq;
    rk[sub][f4] = ak;
    __syncthreads();
    if (tid < 128) {
        const float* rqf = (const float*)&rq[0][0];
        const float* rkf = (const float*)&rk[0][0];
        float s = 0.f, k = 0.f;
        #pragma unroll
        for (int g = 0; g < 8; g++) {
            s += rqf[g * 128 + tid];
            k += rkf[g * 128 + tid];
        }
        g_part[b][ls][0][tid] = s;
        g_part[b][ls][1][tid] = k;
    }
}

// ---------------- 3) fused q/k finalize + softmax + packed B0 + raw att ----------------
__global__ void att_soft() {
    __shared__ float kk[Fn];
    __shared__ float at[16][132];
    __shared__ float ri[16];
    __shared__ float qr[16];
    const int r = blockIdx.x, b = blockIdx.y;
    const int t = threadIdx.x;
    {
        float k = g_bias[1];
        #pragma unroll
        for (int s = 0; s < NSPLIT; s++) k += g_part[b][s][1][t];
        kk[t] = k;
    }
    if (t < 16) {
        float q = g_bias[0];
        #pragma unroll
        for (int s = 0; s < NSPLIT; s++) q += g_part[b][s][0][r * 16 + t];
        qr[t] = q * 0.08838834764831845f;
    }
    __syncthreads();

    const int row = t >> 3, c = t & 7;
    const float tq = qr[row];
    float e[16];
    float m = -1e30f;
    #pragma unroll
    for (int j = 0; j < 16; j++) {
        e[j] = tq * kk[c * 16 + j];
        m = fmaxf(m, e[j]);
    }
    #pragma unroll
    for (int off = 1; off < 8; off <<= 1)
        m = fmaxf(m, __shfl_xor_sync(0xFFFFFFFFu, m, off));
    float sum = 0.f;
    #pragma unroll
    for (int j = 0; j < 16; j++) {
        e[j] = expf(e[j] - m);
        at[row][c * 16 + j] = e[j];
        sum += e[j];
    }
    #pragma unroll
    for (int off = 1; off < 8; off <<= 1)
        sum += __shfl_xor_sync(0xFFFFFFFFu, sum, off);
    if (c == 0) ri[row] = 1.f / sum;
    __syncthreads();

    // raw normalized att rows
    {
        const float rv = ri[row];
        float* dst = &g_att[b][(r * 16 + row) * Fn + c * 16];
        #pragma unroll
        for (int j4 = 0; j4 < 4; j4++) {
            float4 v;
            v.x = at[row][c * 16 + j4 * 4 + 0] * rv;
            v.y = at[row][c * 16 + j4 * 4 + 1] * rv;
            v.z = at[row][c * 16 + j4 * 4 + 2] * rv;
            v.w = at[row][c * 16 + j4 * 4 + 3] * rv;
            ((float4*)dst)[j4] = v;
        }
    }

    #pragma unroll
    for (int eidx = 0; eidx < 4; eidx++) {
        int ee = t + eidx * 128;
        int lane = ee & 31, kk2 = (ee >> 5) & 1, np = (ee >> 6) & 1, wn = ee >> 7;
        int gd = lane >> 2, tg = lane & 3;
        int kr0 = kk2 * 8 + tg, kr1 = kr0 + 4;
        int nA = wn * 32 + np * 16 + gd, nB = nA + 8;
        float4 v;
        v.x = tfr(at[kr0][nA] * ri[kr0]);
        v.y = tfr(at[kr1][nA] * ri[kr1]);
        v.z = tfr(at[kr0][nB] * ri[kr0]);
        v.w = tfr(at[kr1][nB] * ri[kr1]);
        g_Bq0[b][wn * 1024 + np * 512 + (r * 2 + kk2) * 32 + lane] = v;
    }
}

// ---------------- GEMM tile loop: 2 buffers, ONE barrier per tile ----------------
// sequence per tile: wait_group0 -> syncthreads -> issue prefetch(t+1) -> mainloop -> epilogue
// Caller must have issued+committed tile 0's prefetch before calling.
template <int MODE>
__device__ __forceinline__ void gemm_tiles(
    const float* Xin, float* Xout, const float4* Bq,
    const uint32_t* ab32, float* Ab0, float* Ab1, uint32_t aoff,
    const float2* rsc2, const float2* rsh2,
    float2* st_s, float2* st_q,
    int tid, int gid, int tig, int wm, int wn)
{
    for (int t = 0; t < TILES_PER_CTA; t++) {
        CP_WAIT0();
        __syncthreads();                 // publishes tile t data; proves buf[(t+1)&1] reads done

        if (t + 1 < TILES_PER_CTA) {
            const float* src = Xin + (size_t)(t + 1) * TILE_L * Fn;
            #pragma unroll
            for (int i = tid; i < 4096; i += 512)
                cp16(ab32[(t + 1) & 1] + ((i >> 5) * 132 + (i & 31) * 4) * 4, src + (size_t)i * 4);
            CP_COMMIT();
        }

        const uint32_t abase = ab32[t & 1] + aoff;
        float* const buf = (t & 1) ? Ab1 : Ab0;

        float c[2][4][4];
        #pragma unroll
        for (int mi = 0; mi < 2; mi++)
            #pragma unroll
            for (int ni = 0; ni < 4; ni++)
                #pragma unroll
                for (int j = 0; j < 4; j++) c[mi][ni][j] = 0.f;

        #pragma unroll
        for (int ks = 0; ks < 16; ks++) {
            uint32_t a[2][4];
            LDSM4(a[0][0], a[0][1], a[0][2], a[0][3], abase + ks * 32);
            LDSM4(a[1][0], a[1][1], a[1][2], a[1][3], abase + 16 * 132 * 4 + ks * 32);
            #pragma unroll
            for (int np = 0; np < 2; np++) {
                float4 bv = __ldg(Bq + np * 512 + ks * 32);
                uint32_t b0 = __float_as_uint(bv.x), b1 = __float_as_uint(bv.y);
                uint32_t b2 = __float_as_uint(bv.z), b3 = __float_as_uint(bv.w);
                MMA_TF32(c[0][2 * np],     a[0], b0, b1);
                MMA_TF32(c[0][2 * np + 1], a[0], b2, b3);
                MMA_TF32(c[1][2 * np],     a[1], b0, b1);
                MMA_TF32(c[1][2 * np + 1], a[1], b2, b3);
            }
        }

        float* Yt = Xout + (size_t)t * TILE_L * Fn;
        #pragma unroll
        for (int mi = 0; mi < 2; mi++)
            #pragma unroll
            for (int ni = 0; ni < 4; ni++) {
                const int r0 = wm * 32 + mi * 16 + gid;
                const int col = wn * 32 + ni * 8 + tig * 2;
                float2 x0 = *(float2*)&buf[r0 * 132 + col];
                float2 x1 = *(float2*)&buf[(r0 + 8) * 132 + col];
                float2 o0, o1;
                if (MODE == 1) {
                    o0.x = c[mi][ni][0] + fmaf(x0.x, rsc2[ni].x, rsh2[ni].x);
                    o0.y = c[mi][ni][1] + fmaf(x0.y, rsc2[ni].y, rsh2[ni].y);
                    o1.x = c[mi][ni][2] + fmaf(x1.x, rsc2[ni].x, rsh2[ni].x);
                    o1.y = c[mi][ni][3] + fmaf(x1.y, rsc2[ni].y, rsh2[ni].y);
                    *(float2*)&Yt[(size_t)r0 * Fn + col] = o0;
                    *(float2*)&Yt[(size_t)(r0 + 8) * Fn + col] = o1;
                } else {
                    o0.x = c[mi][ni][0] + x0.x;
                    o0.y = c[mi][ni][1] + x0.y;
                    o1.x = c[mi][ni][2] + x1.x;
                    o1.y = c[mi][ni][3] + x1.y;
                }
                st_s[ni].x += o0.x + o1.x;
                st_s[ni].y += o0.y + o1.y;
                st_q[ni].x += fmaf(o0.x, o0.x, o1.x * o1.x);
                st_q[ni].y += fmaf(o0.y, o0.y, o1.y * o1.y);
            }
        // no trailing barrier: buf[(t)&1] is protected by the next tile's start barrier
    }
}

__device__ __forceinline__ void reduce_stats(
    float2* st_s, float2* st_q, float4* red,
    int tid, int w, int gid, int tig, float* srow, float* qrow)
{
    #pragma unroll
    for (int ni = 0; ni < 4; ni++) {
        #pragma unroll
        for (int off = 4; off < 32; off <<= 1) {
            st_s[ni].x += __shfl_xor_sync(0xFFFFFFFFu, st_s[ni].x, off);
            st_s[ni].y += __shfl_xor_sync(0xFFFFFFFFu, st_s[ni].y, off);
            st_q[ni].x += __shfl_xor_sync(0xFFFFFFFFu, st_q[ni].x, off);
            st_q[ni].y += __shfl_xor_sync(0xFFFFFFFFu, st_q[ni].y, off);
        }
        if (gid == 0)
            red[w * 16 + ni * 4 + tig] = make_float4(st_s[ni].x, st_s[ni].y, st_q[ni].x, st_q[ni].y);
    }
    __syncthreads();
    if (tid < 128) {
        const int f = tid;
        const int fwn = f >> 5, fni = (f >> 3) & 3, ftg = (f >> 1) & 3, xy = f & 1;
        float s = 0.f, q = 0.f;
        #pragma unroll
        for (int m = 0; m < 4; m++) {
            float4 v = red[(m * 4 + fwn) * 16 + fni * 4 + ftg];
            s += xy ? v.y : v.x;
            q += xy ? v.w : v.z;
        }
        srow[f] = s;
        qrow[f] = q;
    }
    __syncthreads();
}

// ---------------- 4) persistent fused kernel ----------------
__global__ __launch_bounds__(512, 1)
void mega(const float* __restrict__ x, const float* __restrict__ ffw,
          const float* __restrict__ ffb, const float* __restrict__ gamma,
          const float* __restrict__ beta, float* __restrict__ out)
{
    extern __shared__ float smm[];
    float* const Ab0 = smm;
    float* const Ab1 = smm + FO_A1;
    float4* const red = (float4*)(smm + FO_RED);
    float* const tab = smm + FO_TAB;

    const int tid = threadIdx.x, lane = tid & 31, w = tid >> 5;
    const int gid = lane >> 2, tig = lane & 3;
    const int wm = w >> 2, wn = w & 3;
    const int gx = blockIdx.x, b = blockIdx.y;

    const size_t base = ((size_t)b * Ln + (size_t)gx * TILES_PER_CTA * TILE_L) * Fn;
    uint32_t ab32[2] = { smem_u32(Ab0), smem_u32(Ab1) };
    const uint32_t lrow = lane & 15;
    const uint32_t lcol = (lane >> 4) * 4;
    const uint32_t aoff = ((wm * 32 + lrow) * 132 + lcol) * 4;

    float2 st_s[4], st_q[4];
    float2 unit_sc[4], zero_sh[4];
    #pragma unroll
    for (int ni = 0; ni < 4; ni++) {
        st_s[ni] = make_float2(0.f, 0.f);
        st_q[ni] = make_float2(0.f, 0.f);
        unit_sc[ni] = make_float2(1.f, 1.f);
        zero_sh[ni] = make_float2(0.f, 0.f);
    }

    // prologue: tile-0 prefetch for phase 0
    #pragma unroll
    for (int i = tid; i < 4096; i += 512)
        cp16(ab32[0] + ((i >> 5) * 132 + (i & 31) * 4) * 4, x + base + (size_t)i * 4);
    CP_COMMIT();

    // ===== phase 0: stats of x2 = x + x@att (NO stores) =====
    gemm_tiles<0>(x + base, (float*)nullptr, &g_Bq0[b][0] + wn * 1024 + lane,
                  ab32, Ab0, Ab1, aoff, unit_sc, zero_sh, st_s, st_q,
                  tid, gid, tig, wm, wn);
    reduce_stats(st_s, st_q, red, tid, w, gid, tig,
                 &g_statA[b][gx][0][0], &g_statA[b][gx][1][0]);

    // hoisted phase-1 tile-0 prefetch (A = x, read-only)
    #pragma unroll
    for (int i = tid; i < 4096; i += 512)
        cp16(ab32[0] + ((i >> 5) * 132 + (i & 31) * 4) * 4, x + base + (size_t)i * 4);
    CP_COMMIT();

    // sync 0: all 4 CTAs of this batch (stats complete)
    if (tid == 0) {
        __threadfence();
        atomicAdd(&g_cnt0[b], 1);
        while (atomicAdd(&g_cnt0[b], 0) < GRIDX) __nanosleep(64);
    }
    __syncthreads();

    // sc / sh / rsh
    if (tid < 128) {
        float s = 0.f, q = 0.f;
        #pragma unroll
        for (int t = 0; t < GRIDX; t++) {
            s += g_statA[b][t][0][tid];
            q += g_statA[b][t][1][tid];
        }
        const float inv = 1.f / (float)Ln;
        float m = s * inv;
        float v = q * inv - m * m;
        float rs = rsqrtf(v + 1e-5f);
        float sc = rs * gamma[tid];
        tab[tid] = sc;
        tab[128 + tid] = fmaf(-m, sc, beta[tid]);
    }
    __syncthreads();
    if (tid < 128) {
        float bias2 = ffb[tid];
        const float4* wr = (const float4*)&ffw[tid * Fn];
        #pragma unroll 8
        for (int k4 = 0; k4 < 32; k4++) {
            float4 wv = __ldg(wr + k4);
            bias2 = fmaf(tab[128 + k4 * 4],     wv.x, bias2);
            bias2 = fmaf(tab[128 + k4 * 4 + 1], wv.y, bias2);
            bias2 = fmaf(tab[128 + k4 * 4 + 2], wv.z, bias2);
            bias2 = fmaf(tab[128 + k4 * 4 + 3], wv.w, bias2);
        }
        tab[256 + tid] = tab[128 + tid] + bias2;
    }
    __syncthreads();

    // load att pre-scaled by sc into Ab1 (NOTE: phase-1 tile-0 prefetch went to Ab0)
    {
        const float4* srcA = (const float4*)&g_att[b][0];
        const float4* sc4 = (const float4*)tab;
        #pragma unroll
        for (int i = tid; i < 4096; i += 512) {
            float4 v = __ldg(srcA + i);
            float4 s = sc4[i & 31];
            v.x *= s.x; v.y *= s.y; v.z *= s.z; v.w *= s.w;
            *(float4*)&Ab1[(i >> 5) * 132 + (i & 31) * 4] = v;
        }
    }
    __syncthreads();

    // build this CTA's quarter of C:
    // C[n,f] = sc[f]*W[n,f] + attsc[f][n] + sum_j attsc[f][j]*W[n,j]
    {
        const int ks = (tid >> 5) & 15, lane5 = tid & 31;
        const int gd = lane5 >> 2, tg = lane5 & 3;
        const int f0 = ks * 8 + tg, f1 = f0 + 4;
        const int n0 = gx * 32 + gd;
        const int n2 = n0 + 16;
        const float4* A0 = (const float4*)&Ab1[f0 * 132];
        const float4* A1 = (const float4*)&Ab1[f1 * 132];
        const float4* W0 = (const float4*)&ffw[(n0)      * Fn];
        const float4* W1 = (const float4*)&ffw[(n0 + 8)  * Fn];
        const float4* W2 = (const float4*)&ffw[(n2)      * Fn];
        const float4* W3 = (const float4*)&ffw[(n2 + 8)  * Fn];
        float d[4][2] = {{0.f,0.f},{0.f,0.f},{0.f,0.f},{0.f,0.f}};
        #pragma unroll 4
        for (int k4 = 0; k4 < 32; k4++) {
            float4 a0 = A0[k4], a1 = A1[k4];
            float4 wv;
            wv = __ldg(W0 + k4); d[0][0] = dot4(a0, wv, d[0][0]); d[0][1] = dot4(a1, wv, d[0][1]);
            wv = __ldg(W1 + k4); d[1][0] = dot4(a0, wv, d[1][0]); d[1][1] = dot4(a1, wv, d[1][1]);
            wv = __ldg(W2 + k4); d[2][0] = dot4(a0, wv, d[2][0]); d[2][1] = dot4(a1, wv, d[2][1]);
            wv = __ldg(W3 + k4); d[3][0] = dot4(a0, wv, d[3][0]); d[3][1] = dot4(a1, wv, d[3][1]);
        }
        const float scf0 = tab[f0], scf1 = tab[f1];
        const int nn[4] = { n0, n0 + 8, n2, n2 + 8 };
        float vv[4][2];
        #pragma unroll
        for (int q = 0; q < 4; q++) {
            int n = nn[q];
            vv[q][0] = d[q][0] + scf0 * __ldg(&ffw[n * Fn + f0]) + Ab1[f0 * 132 + n];
            vv[q][1] = d[q][1] + scf1 * __ldg(&ffw[n * Fn + f1]) + Ab1[f1 * 132 + n];
        }
        float4 out0, out1;
        out0.x = tfr(vv[0][0]); out0.y = tfr(vv[0][1]);
        out0.z = tfr(vv[1][0]); out0.w = tfr(vv[1][1]);
        out1.x = tfr(vv[2][0]); out1.y = tfr(vv[2][1]);
        out1.z = tfr(vv[3][0]); out1.w = tfr(vv[3][1]);
        g_Bq1[b][gx * 1024 + 0   + ks * 32 + lane5] = out0;
        g_Bq1[b][gx * 1024 + 512 + ks * 32 + lane5] = out1;
    }

    // sync 1: all 4 CTAs finished their quarter of C
    if (tid == 0) {
        __threadfence();
        atomicAdd(&g_cnt1[b], 1);
        while (atomicAdd(&g_cnt1[b], 0) < GRIDX) __nanosleep(64);
    }
    __syncthreads();

    float2 rsc2[4], rsh2[4];
    #pragma unroll
    for (int ni = 0; ni < 4; ni++) {
        int col = wn * 32 + ni * 8 + tig * 2;
        rsc2[ni] = *(const float2*)&tab[col];
        rsh2[ni] = *(const float2*)&tab[256 + col];
        st_s[ni] = make_float2(0.f, 0.f);
        st_q[ni] = make_float2(0.f, 0.f);
    }

    // ===== phase 1: out_raw = x@C^T + x*sc + rsh (tile-0 prefetch already issued) =====
    gemm_tiles<1>(x + base, out + base, &g_Bq1[b][0] + wn * 1024 + lane,
                  ab32, Ab0, Ab1, aoff, rsc2, rsh2, st_s, st_q,
                  tid, gid, tig, wm, wn);
    reduce_stats(st_s, st_q, red, tid, w, gid, tig,
                 &g_statB[b][gx][0][0], &g_statB[b][gx][1][0]);

    // sync 2
    if (tid == 0) {
        __threadfence();
        atomicAdd(&g_cnt2[b], 1);
        while (atomicAdd(&g_cnt2[b], 0) < GRIDX) __nanosleep(64);
    }
    __syncthreads();

    if (tid < 128) {
        float s = 0.f, q = 0.f;
        #pragma unroll
        for (int t = 0; t < GRIDX; t++) {
            s += g_statB[b][t][0][tid];
            q += g_statB[b][t][1][tid];
        }
        const float inv = 1.f / (float)Ln;
        float m = s * inv;
        float v = q * inv - m * m;
        float rs = rsqrtf(v + 1e-5f);
        float sc = rs * gamma[tid];
        tab[tid] = sc;
        tab[128 + tid] = fmaf(-m, sc, beta[tid]);
    }
    __syncthreads();

    const float4* s4t = (const float4*)tab;
    const float4* h4t = (const float4*)(tab + 128);
    for (int t = 0; t < TILES_PER_CTA; t++) {
        float4* Y4 = (float4*)(out + base + (size_t)t * TILE_L * Fn);
        #pragma unroll
        for (int j = 0; j < 8; j++) {
            int i = tid + 512 * j;
            float4 v = Y4[i];
            int fq = i & 31;
            float4 s = s4t[fq], h = h4t[fq];
            v.x = fmaf(v.x, s.x, h.x); v.y = fmaf(v.y, s.y, h.y);
            v.z = fmaf(v.z, s.z, h.z); v.w = fmaf(v.w, s.w, h.w);
            Y4[i] = v;
        }
    }
}

// ---------------- launch ----------------
extern "C" void kernel_launch(void* const* d_in, const int* in_sizes, int n_in,
                              void* d_out, int out_size) {
    const float* x     = (const float*)d_in[0];
    const float* qw    = (const float*)d_in[1];
    const float* qb    = (const float*)d_in[2];
    const float* kw    = (const float*)d_in[3];
    const float* kb    = (const float*)d_in[4];
    const float* ffw   = (const float*)d_in[5];
    const float* ffb   = (const float*)d_in[6];
    const float* gamma = (const float*)d_in[7];
    const float* beta  = (const float*)d_in[8];
    float* out = (float*)d_out;

    cudaFuncSetAttribute((const void*)mega,
                         cudaFuncAttributeMaxDynamicSharedMemorySize, MEGA_SMEM);

    coef_kernel<<<(Ln + 255) / 256, 256>>>(qw, qb, kw, kb);
    qk_partial<<<dim3(NSPLIT, Bn), 256>>>(x);
    att_soft<<<dim3(8, Bn), 128>>>();
    mega<<<dim3(GRIDX, Bn), 512, MEGA_SMEM>>>(x, ffw, ffb, gamma, beta, out);
}